// round 1
// baseline (speedup 1.0000x reference)
#include <cuda_runtime.h>
#include <cuda_bf16.h>
#include <cstdint>

// RotatedPSRoIAlign:
//   feature_maps: (B=8, C=256, H=200, W=200) float32, NCHW
//   rois:         (N, 6) float32  [b, xc, yc, w, h(unused), ang]
//   out:          (N, C, 7, 7) float32
//
// Grid: one CTA per roi, 256 threads.
// Phase 1: threads 0..48 compute per-point geometry (base offset + 4
//          validity-folded bilinear weights) into smem.
// Phase 2: all 256 threads sweep the roi's 12544 outputs in LINEAR output
//          order (j = i*256 + tid) -> perfectly coalesced STG. Gather loads
//          are inherently scattered in NCHW; zero-weight corners skip the
//          load entirely (predicated LDG).

#define OUT_H 7
#define OUT_W 7
#define NPTS  (OUT_H * OUT_W)   // 49
#define CCH   256
#define HH    200
#define WW    200
#define PLANE (HH * WW)         // 40000
#define PER_ROI (CCH * NPTS)    // 12544

__global__ __launch_bounds__(256, 8)
void rot_psroi_kernel(const float* __restrict__ fm,
                      const float* __restrict__ rois,
                      float* __restrict__ out,
                      int n_rois)
{
    __shared__ float4 s_w[NPTS];   // per-point corner weights (validity folded)
    __shared__ int    s_ob[NPTS];  // per-point base offset y0*W + x0

    const int n = blockIdx.x;
    if (n >= n_rois) return;
    const int t = threadIdx.x;

    // Per-roi scalars (broadcast load, one sector)
    const float bf  = rois[n * 6 + 0];
    const float xc  = rois[n * 6 + 1];
    const float yc  = rois[n * 6 + 2];
    const float ang = rois[n * 6 + 5];
    const int   b   = (int)bf;

    if (t < NPTS) {
        const int oy = t / OUT_W;
        const int ox = t - oy * OUT_W;
        // linspace(-1, 1, 7): step = 2/6
        const float gy = -1.0f + (float)oy * (2.0f / 6.0f);
        const float gx = -1.0f + (float)ox * (2.0f / 6.0f);
        const float c = cosf(ang);
        const float s = sinf(ang);
        const float xn = c * gx - s * gy + xc;
        const float yn = s * gx + c * gy + yc;
        const float ix = (xn + 1.0f) * 0.5f * (float)(WW - 1);
        const float iy = (yn + 1.0f) * 0.5f * (float)(HH - 1);
        const float x0f = floorf(ix);
        const float y0f = floorf(iy);
        const float x1f = x0f + 1.0f;
        const float y1f = y0f + 1.0f;
        const float wx1 = ix - x0f;
        const float wx0 = 1.0f - wx1;
        const float wy1 = iy - y0f;
        const float wy0 = 1.0f - wy1;
        const float vx0 = (x0f >= 0.0f && x0f <= (float)(WW - 1)) ? 1.0f : 0.0f;
        const float vx1 = (x1f >= 0.0f && x1f <= (float)(WW - 1)) ? 1.0f : 0.0f;
        const float vy0 = (y0f >= 0.0f && y0f <= (float)(HH - 1)) ? 1.0f : 0.0f;
        const float vy1 = (y1f >= 0.0f && y1f <= (float)(HH - 1)) ? 1.0f : 0.0f;

        float4 w;
        w.x = wy0 * wx0 * vy0 * vx0;   // (y0, x0)
        w.y = wy0 * wx1 * vy0 * vx1;   // (y0, x1) = +1
        w.z = wy1 * wx0 * vy1 * vx0;   // (y1, x0) = +W
        w.w = wy1 * wx1 * vy1 * vx1;   // (y1, x1) = +W+1
        s_w[t]  = w;
        s_ob[t] = (int)y0f * WW + (int)x0f;
    }
    __syncthreads();

    const float* __restrict__ base = fm + (size_t)b * (size_t)CCH * PLANE;
    float* __restrict__ outp = out + (size_t)n * PER_ROI;

    // 49 iterations * 256 threads = 12544 = exactly one roi's outputs
#pragma unroll 4
    for (int i = 0; i < NPTS; ++i) {
        const int j = i * 256 + t;          // linear output index within roi
        const int c = j / NPTS;             // channel  (div by 49 -> mul/shift)
        const int p = j - c * NPTS;         // point
        const float4 w = s_w[p];
        const int    ob = s_ob[p];
        const float* __restrict__ pl = base + c * PLANE + ob;

        float acc;
        {
            float v = (w.x != 0.0f) ? __ldg(pl) : 0.0f;
            acc = w.x * v;
        }
        {
            float v = (w.y != 0.0f) ? __ldg(pl + 1) : 0.0f;
            acc = fmaf(w.y, v, acc);
        }
        {
            float v = (w.z != 0.0f) ? __ldg(pl + WW) : 0.0f;
            acc = fmaf(w.z, v, acc);
        }
        {
            float v = (w.w != 0.0f) ? __ldg(pl + WW + 1) : 0.0f;
            acc = fmaf(w.w, v, acc);
        }
        outp[j] = acc;
    }
}

extern "C" void kernel_launch(void* const* d_in, const int* in_sizes, int n_in,
                              void* d_out, int out_size)
{
    const float* fm   = (const float*)d_in[0];
    const float* rois = (const float*)d_in[1];
    float* out        = (float*)d_out;
    const int n_rois  = in_sizes[1] / 6;

    rot_psroi_kernel<<<n_rois, 256>>>(fm, rois, out, n_rois);
}

// round 6
// speedup vs baseline: 1.1561x; 1.1561x over previous
#include <cuda_runtime.h>
#include <cuda_bf16.h>
#include <cstdint>

// RotatedPSRoIAlign:
//   feature_maps: (B=8, C=256, H=200, W=200) float32, NCHW
//   rois:         (N, 6) float32  [b, xc, yc, w, h(unused), ang]
//   out:          (N, C, 7, 7) float32
//
// One CTA per roi, 256 threads.
// Phase 1: threads 0..48 compute per-point geometry into smem:
//   - validity-folded bilinear weights (float4)
//   - one 16B-aligned float4 base per row; x0/x1 are selected by independent
//     indices fr0 = ex0-a (0..3), fr1 = ex1-a (0..4). fr1==4 -> one extra
//     scalar load. Independent clamping of x0/x1 fixes the x0==-1 case.
// Phase 2: 256 threads sweep the roi's 12544 outputs in linear output order
//   (coalesced STG). Row loads are predicated on the row's weight pair being
//   nonzero; all issued addresses are clamped in-plane.

#define OUT_H 7
#define OUT_W 7
#define NPTS  (OUT_H * OUT_W)   // 49
#define CCH   256
#define HH    200
#define WW    200
#define PLANE (HH * WW)         // 40000
#define PER_ROI (CCH * NPTS)    // 12544

__device__ __forceinline__ float sel_idx(float4 v, int k) {
    float r = v.x;
    r = (k == 1) ? v.y : r;
    r = (k == 2) ? v.z : r;
    r = (k == 3) ? v.w : r;
    return r;
}

__global__ __launch_bounds__(256)
void rot_psroi_kernel(const float* __restrict__ fm,
                      const float* __restrict__ rois,
                      float* __restrict__ out,
                      int n_rois)
{
    __shared__ float4 s_w[NPTS];    // folded corner weights (w00,w01,w10,w11)
    __shared__ int    s_o0[NPTS];   // aligned elem offset, row y0 (ey0*W + a)
    __shared__ int    s_o1[NPTS];   // aligned elem offset, row y1
    __shared__ int    s_fr[NPTS];   // fr0 | (fr1 << 8)

    const int n = blockIdx.x;
    if (n >= n_rois) return;
    const int t = threadIdx.x;

    const float bf  = rois[n * 6 + 0];
    const float xc  = rois[n * 6 + 1];
    const float yc  = rois[n * 6 + 2];
    const float ang = rois[n * 6 + 5];
    const int   b   = (int)bf;

    if (t < NPTS) {
        const int oy = t / OUT_W;
        const int ox = t - oy * OUT_W;
        const float gy = -1.0f + (float)oy * (2.0f / 6.0f);
        const float gx = -1.0f + (float)ox * (2.0f / 6.0f);
        const float c = cosf(ang);
        const float s = sinf(ang);
        const float xn = c * gx - s * gy + xc;
        const float yn = s * gx + c * gy + yc;
        const float ix = (xn + 1.0f) * 0.5f * (float)(WW - 1);
        const float iy = (yn + 1.0f) * 0.5f * (float)(HH - 1);
        const float x0f = floorf(ix);
        const float y0f = floorf(iy);
        const float wx1 = ix - x0f;
        const float wx0 = 1.0f - wx1;
        const float wy1 = iy - y0f;
        const float wy0 = 1.0f - wy1;

        const int x0 = (int)x0f;
        const int y0 = (int)y0f;
        const int x1 = x0 + 1;
        const int y1 = y0 + 1;

        const float vx0 = (x0 >= 0 && x0 <= WW - 1) ? 1.0f : 0.0f;
        const float vx1 = (x1 >= 0 && x1 <= WW - 1) ? 1.0f : 0.0f;
        const float vy0 = (y0 >= 0 && y0 <= HH - 1) ? 1.0f : 0.0f;
        const float vy1 = (y1 >= 0 && y1 <= HH - 1) ? 1.0f : 0.0f;

        float4 w;
        w.x = wy0 * wx0 * vy0 * vx0;   // (y0, x0)
        w.y = wy0 * wx1 * vy0 * vx1;   // (y0, x1)
        w.z = wy1 * wx0 * vy1 * vx0;   // (y1, x0)
        w.w = wy1 * wx1 * vy1 * vx1;   // (y1, x1)

        const int ex0 = min(max(x0, 0), WW - 1);
        const int ex1 = min(max(x1, 0), WW - 1);
        const int ey0 = min(max(y0, 0), HH - 1);
        const int ey1 = min(max(y1, 0), HH - 1);
        const int a   = ex0 & ~3;      // 16B-aligned float4 base (in-plane)
        const int fr0 = ex0 - a;       // 0..3
        const int fr1 = ex1 - a;       // 0..4  (0 when x0==-1 -> ex0==ex1==0)

        s_w[t]  = w;
        s_o0[t] = ey0 * WW + a;
        s_o1[t] = ey1 * WW + a;
        s_fr[t] = fr0 | (fr1 << 8);
    }
    __syncthreads();

    const float* __restrict__ base = fm + (size_t)b * (size_t)CCH * PLANE;
    float* __restrict__ outp = out + (size_t)n * PER_ROI;

    const float4 z4 = make_float4(0.f, 0.f, 0.f, 0.f);

#pragma unroll 7
    for (int i = 0; i < NPTS; ++i) {
        const int j = i * 256 + t;          // linear output index within roi
        const int c = j / NPTS;
        const int p = j - c * NPTS;

        const float4 w  = s_w[p];
        const int    o0 = s_o0[p];
        const int    o1 = s_o1[p];
        const int    fp = s_fr[p];
        const int    fr0 = fp & 0xff;
        const int    fr1 = fp >> 8;

        const float* __restrict__ pc = base + c * PLANE;

        const bool r0v = (w.x != 0.0f) | (w.y != 0.0f);
        const bool r1v = (w.z != 0.0f) | (w.w != 0.0f);

        const float4 v0 = r0v ? __ldg((const float4*)(pc + o0)) : z4;
        const float4 v1 = r1v ? __ldg((const float4*)(pc + o1)) : z4;

        const float f00 = sel_idx(v0, fr0);
        const float f10 = sel_idx(v1, fr0);

        float f01, f11;
        if (fr1 < 4) {
            f01 = sel_idx(v0, fr1);
            f11 = sel_idx(v1, fr1);
        } else {
            // x1 sits in the next float4's first slot; a+4 == ex1 <= W-1,
            // so the address is always in-plane. Predicate to save traffic.
            f01 = (w.y != 0.0f) ? __ldg(pc + o0 + 4) : 0.0f;
            f11 = (w.w != 0.0f) ? __ldg(pc + o1 + 4) : 0.0f;
        }

        float acc = w.x * f00;
        acc = fmaf(w.y, f01, acc);
        acc = fmaf(w.z, f10, acc);
        acc = fmaf(w.w, f11, acc);

        outp[j] = acc;
    }
}

extern "C" void kernel_launch(void* const* d_in, const int* in_sizes, int n_in,
                              void* d_out, int out_size)
{
    const float* fm   = (const float*)d_in[0];
    const float* rois = (const float*)d_in[1];
    float* out        = (float*)d_out;
    const int n_rois  = in_sizes[1] / 6;

    rot_psroi_kernel<<<n_rois, 256>>>(fm, rois, out, n_rois);
}